// round 2
// baseline (speedup 1.0000x reference)
#include <cuda_runtime.h>
#include <cuda_bf16.h>
#include <math.h>
#include <stdint.h>

#define N_TOK 16384
#define DIM 768
#define NEXP 8
#define HID 2048
#define CAP 5120
#define ECAP (NEXP*CAP)
#define NP (N_TOK*2)

// ---------------- device scratch (no allocations allowed) ----------------
__device__ int   g_pair_expert[NP];
__device__ float g_pair_weight[NP];
__device__ int   g_pair_slot[NP];
__device__ int   g_slot_token[ECAP];
__device__ int   g_count[NEXP];
__device__ __nv_bfloat16 g_w13bf[(size_t)NEXP*2*HID*DIM];   // 50 MB
__device__ __nv_bfloat16 g_w2bf [(size_t)NEXP*DIM*HID];     // 25 MB
__device__ __nv_bfloat16 g_zbuf [(size_t)ECAP*DIM];         // 63 MB
__device__ __nv_bfloat16 g_hbuf [(size_t)ECAP*HID];         // 168 MB
__device__ float         g_ybuf [(size_t)ECAP*DIM];         // 126 MB

// ---------------- helpers ----------------
__device__ __forceinline__ uint32_t smem_u32(const void* p) {
    return (uint32_t)__cvta_generic_to_shared(p);
}
__device__ __forceinline__ void ldsm_x4(uint32_t& r0, uint32_t& r1, uint32_t& r2, uint32_t& r3, uint32_t a) {
    asm volatile("ldmatrix.sync.aligned.m8n8.x4.shared.b16 {%0,%1,%2,%3},[%4];"
                 : "=r"(r0), "=r"(r1), "=r"(r2), "=r"(r3) : "r"(a));
}
__device__ __forceinline__ void mma16816(float* c, const uint32_t* a, const uint32_t* b) {
    asm volatile("mma.sync.aligned.m16n8k16.row.col.f32.bf16.bf16.f32 "
                 "{%0,%1,%2,%3},{%4,%5,%6,%7},{%8,%9},{%0,%1,%2,%3};"
                 : "+f"(c[0]), "+f"(c[1]), "+f"(c[2]), "+f"(c[3])
                 : "r"(a[0]), "r"(a[1]), "r"(a[2]), "r"(a[3]), "r"(b[0]), "r"(b[1]));
}

// ---------------- weight conversion (fp32 -> bf16) ----------------
__global__ void k_conv13(const float* __restrict__ s) {
    size_t i = ((size_t)blockIdx.x * 256 + threadIdx.x) * 4;
    float4 v = *reinterpret_cast<const float4*>(s + i);
    *reinterpret_cast<__nv_bfloat162*>(g_w13bf + i)     = __floats2bfloat162_rn(v.x, v.y);
    *reinterpret_cast<__nv_bfloat162*>(g_w13bf + i + 2) = __floats2bfloat162_rn(v.z, v.w);
}
__global__ void k_conv2(const float* __restrict__ s) {
    size_t i = ((size_t)blockIdx.x * 256 + threadIdx.x) * 4;
    float4 v = *reinterpret_cast<const float4*>(s + i);
    *reinterpret_cast<__nv_bfloat162*>(g_w2bf + i)     = __floats2bfloat162_rn(v.x, v.y);
    *reinterpret_cast<__nv_bfloat162*>(g_w2bf + i + 2) = __floats2bfloat162_rn(v.z, v.w);
}

// ---------------- router: 1 warp per token ----------------
__global__ void k_router(const float* __restrict__ x, const float* __restrict__ gw) {
    const int warp = threadIdx.x >> 5, lane = threadIdx.x & 31;
    const int t = blockIdx.x * 8 + warp;
    float acc[NEXP];
    #pragma unroll
    for (int e = 0; e < NEXP; e++) acc[e] = 0.f;
    const float* xr = x + (size_t)t * DIM;
    for (int i = lane; i < DIM; i += 32) {
        float xv = xr[i];
        #pragma unroll
        for (int e = 0; e < NEXP; e++) acc[e] += xv * gw[e * DIM + i];
    }
    #pragma unroll
    for (int e = 0; e < NEXP; e++) {
        #pragma unroll
        for (int off = 16; off; off >>= 1)
            acc[e] += __shfl_xor_sync(0xffffffffu, acc[e], off);
    }
    if (lane == 0) {
        int e1 = 0; float l1 = acc[0];
        #pragma unroll
        for (int e = 1; e < NEXP; e++) if (acc[e] > l1) { l1 = acc[e]; e1 = e; }
        int e2 = (e1 == 0) ? 1 : 0; float l2 = acc[e2];
        #pragma unroll
        for (int e = 0; e < NEXP; e++)
            if (e != e1 && acc[e] > l2) { l2 = acc[e]; e2 = e; }
        float w1 = 1.f / (1.f + expf(l2 - l1));   // softmax over {l1,l2}
        g_pair_expert[2 * t]     = e1;
        g_pair_expert[2 * t + 1] = e2;
        g_pair_weight[2 * t]     = w1;
        g_pair_weight[2 * t + 1] = 1.f - w1;
    }
}

// ---------------- dispatch: exact flat-order ranks + capacity ----------------
// 1024 threads, 32 pairs each. No per-thread index array (reg pressure);
// second pass re-reads g_pair_expert (L2-hot).
__global__ __launch_bounds__(1024) void k_dispatch() {
    __shared__ int s[1024][NEXP];
    const int tid = threadIdx.x;
    const int base_p = tid * 32;
    int cnt[NEXP];
    #pragma unroll
    for (int e = 0; e < NEXP; e++) cnt[e] = 0;
    for (int j = 0; j < 32; j++)
        cnt[g_pair_expert[base_p + j]]++;
    #pragma unroll
    for (int e = 0; e < NEXP; e++) s[tid][e] = cnt[e];
    __syncthreads();
    for (int off = 1; off < 1024; off <<= 1) {
        int v[NEXP];
        #pragma unroll
        for (int e = 0; e < NEXP; e++)
            v[e] = s[tid][e] + ((tid >= off) ? s[tid - off][e] : 0);
        __syncthreads();
        #pragma unroll
        for (int e = 0; e < NEXP; e++) s[tid][e] = v[e];
        __syncthreads();
    }
    int basec[NEXP];
    #pragma unroll
    for (int e = 0; e < NEXP; e++) basec[e] = s[tid][e] - cnt[e];
    if (tid < NEXP) g_count[tid] = min(s[1023][tid], CAP);
    for (int j = 0; j < 32; j++) {
        int p = base_p + j;
        int e = g_pair_expert[p];
        int pos = basec[e]++;
        if (pos < CAP) {
            int slot = e * CAP + pos;
            g_pair_slot[p] = slot;
            g_slot_token[slot] = p >> 1;
        } else {
            g_pair_slot[p] = -1;
        }
    }
}

// ---------------- zbuf: RMSNorm(2x)*norm_w -> bf16 per slot ----------------
__global__ void k_zbuf(const float* __restrict__ x, const float* __restrict__ nw) {
    const int slot = blockIdx.x;
    const int e = slot / CAP;
    const int tid = threadIdx.x;
    __nv_bfloat16* zr = g_zbuf + (size_t)slot * DIM;
    const int local = slot - e * CAP;
    if (local >= g_count[e]) {
        #pragma unroll
        for (int j = 0; j < 3; j++) zr[tid + j * 256] = __float2bfloat16(0.f);
        return;
    }
    const int t = g_slot_token[slot];
    const float* xr = x + (size_t)t * DIM;
    float v[3]; float ss = 0.f;
    #pragma unroll
    for (int j = 0; j < 3; j++) { v[j] = xr[tid + j * 256]; ss += v[j] * v[j]; }
    #pragma unroll
    for (int off = 16; off; off >>= 1) ss += __shfl_xor_sync(0xffffffffu, ss, off);
    __shared__ float red[8];
    if ((tid & 31) == 0) red[tid >> 5] = ss;
    __syncthreads();
    float tot = 0.f;
    #pragma unroll
    for (int w = 0; w < 8; w++) tot += red[w];
    // z = 2x; scale = rsqrt(mean(4x^2)+eps)  ->  z*scale = x * 2*rsqrt(4*ss/D+eps)
    float scale = rsqrtf(4.f * tot / (float)DIM + 1e-6f) * 2.f;
    #pragma unroll
    for (int j = 0; j < 3; j++)
        zr[tid + j * 256] = __float2bfloat16(v[j] * scale * nw[e * DIM + tid + j * 256]);
}

// ---------------- GEMM1: gu = z @ w13^T, fused SwiGLU -> hbuf ----------------
// block: 128 rows x 64 h-cols (128 accum cols: 64 g + 64 u), BK=32
__global__ __launch_bounds__(256) void k_gemm1() {
    const int e = blockIdx.z;
    const int row0 = blockIdx.y * 128;
    if (row0 >= g_count[e]) return;
    const int jb = blockIdx.x * 64;
    __shared__ __align__(16) __nv_bfloat16 As[128][40];
    __shared__ __align__(16) __nv_bfloat16 Bs[128][40];
    const int tid = threadIdx.x, lane = tid & 31, wid = tid >> 5;
    const int wm = wid >> 1, wc = wid & 1;
    const __nv_bfloat16* Ag  = g_zbuf  + (size_t)(e * CAP + row0) * DIM;
    const __nv_bfloat16* Bgg = g_w13bf + (size_t)e * (2 * HID) * DIM + (size_t)jb * DIM;
    const __nv_bfloat16* Bgu = g_w13bf + (size_t)e * (2 * HID) * DIM + (size_t)(HID + jb) * DIM;
    const int lr = tid >> 2;          // 0..63
    const int lc = (tid & 3) * 8;     // 0,8,16,24

    float acc[2][8][4];
    #pragma unroll
    for (int i = 0; i < 2; i++)
        #pragma unroll
        for (int j = 0; j < 8; j++)
            #pragma unroll
            for (int q = 0; q < 4; q++) acc[i][j][q] = 0.f;

    uint4 pa0, pa1, pb0, pb1;
    pa0 = *reinterpret_cast<const uint4*>(Ag  + (size_t)lr * DIM + lc);
    pa1 = *reinterpret_cast<const uint4*>(Ag  + (size_t)(lr + 64) * DIM + lc);
    pb0 = *reinterpret_cast<const uint4*>(Bgg + (size_t)lr * DIM + lc);
    pb1 = *reinterpret_cast<const uint4*>(Bgu + (size_t)lr * DIM + lc);
    *reinterpret_cast<uint4*>(&As[lr][lc])      = pa0;
    *reinterpret_cast<uint4*>(&As[lr + 64][lc]) = pa1;
    *reinterpret_cast<uint4*>(&Bs[lr][lc])      = pb0;
    *reinterpret_cast<uint4*>(&Bs[lr + 64][lc]) = pb1;
    __syncthreads();

    const int KT = DIM / 32;  // 24
    for (int kt = 0; kt < KT; kt++) {
        if (kt + 1 < KT) {
            int k0 = (kt + 1) * 32;
            pa0 = *reinterpret_cast<const uint4*>(Ag  + (size_t)lr * DIM + k0 + lc);
            pa1 = *reinterpret_cast<const uint4*>(Ag  + (size_t)(lr + 64) * DIM + k0 + lc);
            pb0 = *reinterpret_cast<const uint4*>(Bgg + (size_t)lr * DIM + k0 + lc);
            pb1 = *reinterpret_cast<const uint4*>(Bgu + (size_t)lr * DIM + k0 + lc);
        }
        #pragma unroll
        for (int ka = 0; ka < 2; ka++) {
            uint32_t af[2][4];
            #pragma unroll
            for (int i = 0; i < 2; i++) {
                uint32_t addr = smem_u32(&As[wm * 32 + i * 16 + (lane & 15)][ka * 16 + ((lane >> 4) << 3)]);
                ldsm_x4(af[i][0], af[i][1], af[i][2], af[i][3], addr);
            }
            uint32_t bfm[8][2];
            #pragma unroll
            for (int jp = 0; jp < 4; jp++) {
                int j0 = jp * 2;
                int m = lane >> 3;                 // 0..3
                int jj = j0 + (m >> 1);
                int brow = (jj < 4) ? (wc * 32 + jj * 8) : (64 + wc * 32 + (jj - 4) * 8);
                uint32_t addr = smem_u32(&Bs[brow + (lane & 7)][ka * 16 + ((m & 1) << 3)]);
                uint32_t r0, r1, r2, r3;
                ldsm_x4(r0, r1, r2, r3, addr);
                bfm[j0][0] = r0; bfm[j0][1] = r1;
                bfm[j0 + 1][0] = r2; bfm[j0 + 1][1] = r3;
            }
            #pragma unroll
            for (int i = 0; i < 2; i++)
                #pragma unroll
                for (int j = 0; j < 8; j++)
                    mma16816(acc[i][j], af[i], bfm[j]);
        }
        __syncthreads();
        if (kt + 1 < KT) {
            *reinterpret_cast<uint4*>(&As[lr][lc])      = pa0;
            *reinterpret_cast<uint4*>(&As[lr + 64][lc]) = pa1;
            *reinterpret_cast<uint4*>(&Bs[lr][lc])      = pb0;
            *reinterpret_cast<uint4*>(&Bs[lr + 64][lc]) = pb1;
            __syncthreads();
        }
    }

    // epilogue: h = silu(g) * u  (atoms 0..3 = g, 4..7 = u, same h columns)
    const int gid = lane >> 2, qid = lane & 3;
    __nv_bfloat16* Hb = g_hbuf + (size_t)(e * CAP + row0) * HID;
    #pragma unroll
    for (int i = 0; i < 2; i++) {
        #pragma unroll
        for (int j = 0; j < 4; j++) {
            int hc = jb + wc * 32 + j * 8 + qid * 2;
            #pragma unroll
            for (int half = 0; half < 2; half++) {
                int r = wm * 32 + i * 16 + gid + half * 8;
                float g0 = acc[i][j][half * 2 + 0], g1 = acc[i][j][half * 2 + 1];
                float u0 = acc[i][j + 4][half * 2 + 0], u1 = acc[i][j + 4][half * 2 + 1];
                float h0 = g0 * u0 / (1.f + __expf(-g0));
                float h1 = g1 * u1 / (1.f + __expf(-g1));
                *reinterpret_cast<__nv_bfloat162*>(Hb + (size_t)r * HID + hc) =
                    __floats2bfloat162_rn(h0, h1);
            }
        }
    }
}

// ---------------- GEMM2: y = h @ w2^T -> ybuf (fp32) ----------------
// block: 128 rows x 64 d-cols, BK=32
__global__ __launch_bounds__(256) void k_gemm2() {
    const int e = blockIdx.z;
    const int row0 = blockIdx.y * 128;
    if (row0 >= g_count[e]) return;
    const int db = blockIdx.x * 64;
    __shared__ __align__(16) __nv_bfloat16 As[128][40];
    __shared__ __align__(16) __nv_bfloat16 Bs[64][40];
    const int tid = threadIdx.x, lane = tid & 31, wid = tid >> 5;
    const int wm = wid >> 1, wc = wid & 1;
    const __nv_bfloat16* Ag = g_hbuf + (size_t)(e * CAP + row0) * HID;
    const __nv_bfloat16* Bg = g_w2bf + (size_t)e * DIM * HID + (size_t)db * HID;
    const int lr = tid >> 2;
    const int lc = (tid & 3) * 8;

    float acc[2][4][4];
    #pragma unroll
    for (int i = 0; i < 2; i++)
        #pragma unroll
        for (int j = 0; j < 4; j++)
            #pragma unroll
            for (int q = 0; q < 4; q++) acc[i][j][q] = 0.f;

    uint4 pa0, pa1, pb0;
    pa0 = *reinterpret_cast<const uint4*>(Ag + (size_t)lr * HID + lc);
    pa1 = *reinterpret_cast<const uint4*>(Ag + (size_t)(lr + 64) * HID + lc);
    pb0 = *reinterpret_cast<const uint4*>(Bg + (size_t)lr * HID + lc);
    *reinterpret_cast<uint4*>(&As[lr][lc])      = pa0;
    *reinterpret_cast<uint4*>(&As[lr + 64][lc]) = pa1;
    *reinterpret_cast<uint4*>(&Bs[lr][lc])      = pb0;
    __syncthreads();

    const int KT = HID / 32;  // 64
    for (int kt = 0; kt < KT; kt++) {
        if (kt + 1 < KT) {
            int k0 = (kt + 1) * 32;
            pa0 = *reinterpret_cast<const uint4*>(Ag + (size_t)lr * HID + k0 + lc);
            pa1 = *reinterpret_cast<const uint4*>(Ag + (size_t)(lr + 64) * HID + k0 + lc);
            pb0 = *reinterpret_cast<const uint4*>(Bg + (size_t)lr * HID + k0 + lc);
        }
        #pragma unroll
        for (int ka = 0; ka < 2; ka++) {
            uint32_t af[2][4];
            #pragma unroll
            for (int i = 0; i < 2; i++) {
                uint32_t addr = smem_u32(&As[wm * 32 + i * 16 + (lane & 15)][ka * 16 + ((lane >> 4) << 3)]);
                ldsm_x4(af[i][0], af[i][1], af[i][2], af[i][3], addr);
            }
            uint32_t bfm[4][2];
            #pragma unroll
            for (int jp = 0; jp < 2; jp++) {
                int j0 = jp * 2;
                int m = lane >> 3;
                int jj = j0 + (m >> 1);
                int brow = wc * 32 + jj * 8;
                uint32_t addr = smem_u32(&Bs[brow + (lane & 7)][ka * 16 + ((m & 1) << 3)]);
                uint32_t r0, r1, r2, r3;
                ldsm_x4(r0, r1, r2, r3, addr);
                bfm[j0][0] = r0; bfm[j0][1] = r1;
                bfm[j0 + 1][0] = r2; bfm[j0 + 1][1] = r3;
            }
            #pragma unroll
            for (int i = 0; i < 2; i++)
                #pragma unroll
                for (int j = 0; j < 4; j++)
                    mma16816(acc[i][j], af[i], bfm[j]);
        }
        __syncthreads();
        if (kt + 1 < KT) {
            *reinterpret_cast<uint4*>(&As[lr][lc])      = pa0;
            *reinterpret_cast<uint4*>(&As[lr + 64][lc]) = pa1;
            *reinterpret_cast<uint4*>(&Bs[lr][lc])      = pb0;
            __syncthreads();
        }
    }

    const int gid = lane >> 2, qid = lane & 3;
    float* Yb = g_ybuf + (size_t)(e * CAP + row0) * DIM;
    #pragma unroll
    for (int i = 0; i < 2; i++) {
        #pragma unroll
        for (int j = 0; j < 4; j++) {
            int dc = db + wc * 32 + j * 8 + qid * 2;
            #pragma unroll
            for (int half = 0; half < 2; half++) {
                int r = wm * 32 + i * 16 + gid + half * 8;
                float2 v = make_float2(acc[i][j][half * 2 + 0], acc[i][j][half * 2 + 1]);
                *reinterpret_cast<float2*>(Yb + (size_t)r * DIM + dc) = v;
            }
        }
    }
}

// ---------------- combine ----------------
__global__ void k_combine(const float* __restrict__ x, float* __restrict__ out) {
    const int t = blockIdx.x, tid = threadIdx.x;
    int s0 = g_pair_slot[2 * t], s1 = g_pair_slot[2 * t + 1];
    float w0 = g_pair_weight[2 * t], w1 = g_pair_weight[2 * t + 1];
    if (s0 < 0) w0 = 0.f;
    if (s1 < 0) w1 = 0.f;
    const float wsum = w0 + w1;
    const float* y0 = g_ybuf + (size_t)(s0 < 0 ? 0 : s0) * DIM;
    const float* y1 = g_ybuf + (size_t)(s1 < 0 ? 0 : s1) * DIM;
    #pragma unroll
    for (int j = 0; j < 3; j++) {
        int d = tid + j * 256;
        float v = wsum * x[(size_t)t * DIM + d];
        if (s0 >= 0) v += w0 * y0[d];
        if (s1 >= 0) v += w1 * y1[d];
        out[(size_t)t * DIM + d] = v;
    }
}

// ---------------- launch ----------------
extern "C" void kernel_launch(void* const* d_in, const int* in_sizes, int n_in,
                              void* d_out, int out_size) {
    const float* x      = (const float*)d_in[0];
    const float* gate_w = (const float*)d_in[1];
    const float* w13    = (const float*)d_in[2];
    const float* w2     = (const float*)d_in[3];
    const float* norm_w = (const float*)d_in[4];
    float* out = (float*)d_out;

    k_conv13<<<(NEXP * 2 * HID * DIM) / 1024, 256>>>(w13);
    k_conv2 <<<(NEXP * DIM * HID) / 1024, 256>>>(w2);
    k_router<<<N_TOK / 8, 256>>>(x, gate_w);
    k_dispatch<<<1, 1024>>>();
    k_zbuf<<<ECAP, 256>>>(x, norm_w);
    k_gemm1<<<dim3(HID / 64, CAP / 128, NEXP), 256>>>();
    k_gemm2<<<dim3(DIM / 64, CAP / 128, NEXP), 256>>>();
    k_combine<<<N_TOK, 256>>>(x, out);
}

// round 3
// speedup vs baseline: 1.1018x; 1.1018x over previous
#include <cuda_runtime.h>
#include <cuda_bf16.h>
#include <math.h>
#include <stdint.h>

#define N_TOK 16384
#define DIM 768
#define NEXP 8
#define HID 2048
#define CAP 5120
#define ECAP (NEXP*CAP)
#define NP (N_TOK*2)

// ---------------- device scratch (no allocations allowed) ----------------
__device__ int   g_pair_expert[NP];
__device__ float g_pair_weight[NP];
__device__ int   g_pair_slot[NP];
__device__ int   g_slot_token[ECAP];
__device__ int   g_count[NEXP];
__device__ __nv_bfloat16 g_w13bf[(size_t)NEXP*2*HID*DIM];   // 50 MB
__device__ __nv_bfloat16 g_w2bf [(size_t)NEXP*DIM*HID];     // 25 MB
__device__ __nv_bfloat16 g_zbuf [(size_t)ECAP*DIM];         // 63 MB
__device__ __nv_bfloat16 g_hbuf [(size_t)ECAP*HID];         // 168 MB
__device__ float         g_ybuf [(size_t)ECAP*DIM];         // 126 MB

// ---------------- helpers ----------------
__device__ __forceinline__ uint32_t smem_u32(const void* p) {
    return (uint32_t)__cvta_generic_to_shared(p);
}
__device__ __forceinline__ void ldsm_x4(uint32_t& r0, uint32_t& r1, uint32_t& r2, uint32_t& r3, uint32_t a) {
    asm volatile("ldmatrix.sync.aligned.m8n8.x4.shared.b16 {%0,%1,%2,%3},[%4];"
                 : "=r"(r0), "=r"(r1), "=r"(r2), "=r"(r3) : "r"(a));
}
__device__ __forceinline__ void mma16816(float* c, const uint32_t* a, const uint32_t* b) {
    asm volatile("mma.sync.aligned.m16n8k16.row.col.f32.bf16.bf16.f32 "
                 "{%0,%1,%2,%3},{%4,%5,%6,%7},{%8,%9},{%0,%1,%2,%3};"
                 : "+f"(c[0]), "+f"(c[1]), "+f"(c[2]), "+f"(c[3])
                 : "r"(a[0]), "r"(a[1]), "r"(a[2]), "r"(a[3]), "r"(b[0]), "r"(b[1]));
}
__device__ __forceinline__ void cp16(void* s, const void* g) {
    asm volatile("cp.async.cg.shared.global [%0],[%1],16;\n"
                 :: "r"(smem_u32(s)), "l"(g) : "memory");
}
#define CP_COMMIT() asm volatile("cp.async.commit_group;\n" ::: "memory")
#define CP_WAIT0()  asm volatile("cp.async.wait_group 0;\n" ::: "memory")

// ---------------- weight conversion (fp32 -> bf16) ----------------
__global__ void k_conv13(const float* __restrict__ s) {
    size_t i = ((size_t)blockIdx.x * 256 + threadIdx.x) * 4;
    float4 v = *reinterpret_cast<const float4*>(s + i);
    *reinterpret_cast<__nv_bfloat162*>(g_w13bf + i)     = __floats2bfloat162_rn(v.x, v.y);
    *reinterpret_cast<__nv_bfloat162*>(g_w13bf + i + 2) = __floats2bfloat162_rn(v.z, v.w);
}
__global__ void k_conv2(const float* __restrict__ s) {
    size_t i = ((size_t)blockIdx.x * 256 + threadIdx.x) * 4;
    float4 v = *reinterpret_cast<const float4*>(s + i);
    *reinterpret_cast<__nv_bfloat162*>(g_w2bf + i)     = __floats2bfloat162_rn(v.x, v.y);
    *reinterpret_cast<__nv_bfloat162*>(g_w2bf + i + 2) = __floats2bfloat162_rn(v.z, v.w);
}

// ---------------- router: 1 warp per token ----------------
__global__ void k_router(const float* __restrict__ x, const float* __restrict__ gw) {
    const int warp = threadIdx.x >> 5, lane = threadIdx.x & 31;
    const int t = blockIdx.x * 8 + warp;
    float acc[NEXP];
    #pragma unroll
    for (int e = 0; e < NEXP; e++) acc[e] = 0.f;
    const float* xr = x + (size_t)t * DIM;
    for (int i = lane; i < DIM; i += 32) {
        float xv = xr[i];
        #pragma unroll
        for (int e = 0; e < NEXP; e++) acc[e] += xv * gw[e * DIM + i];
    }
    #pragma unroll
    for (int e = 0; e < NEXP; e++) {
        #pragma unroll
        for (int off = 16; off; off >>= 1)
            acc[e] += __shfl_xor_sync(0xffffffffu, acc[e], off);
    }
    if (lane == 0) {
        int e1 = 0; float l1 = acc[0];
        #pragma unroll
        for (int e = 1; e < NEXP; e++) if (acc[e] > l1) { l1 = acc[e]; e1 = e; }
        int e2 = (e1 == 0) ? 1 : 0; float l2 = acc[e2];
        #pragma unroll
        for (int e = 0; e < NEXP; e++)
            if (e != e1 && acc[e] > l2) { l2 = acc[e]; e2 = e; }
        float w1 = 1.f / (1.f + expf(l2 - l1));   // softmax over {l1,l2}
        g_pair_expert[2 * t]     = e1;
        g_pair_expert[2 * t + 1] = e2;
        g_pair_weight[2 * t]     = w1;
        g_pair_weight[2 * t + 1] = 1.f - w1;
    }
}

// ---------------- dispatch: exact flat-order ranks + capacity ----------------
// Fully register-resident counters (unrolled predicated updates — no dynamic
// array indexing, no local memory). int4 vectorized expert loads.
__global__ __launch_bounds__(1024) void k_dispatch() {
    __shared__ int s[1024][NEXP];
    const int tid = threadIdx.x;
    const int base_p = tid * 32;
    const int4* ep = reinterpret_cast<const int4*>(g_pair_expert + base_p);

    int cnt[NEXP];
    #pragma unroll
    for (int e = 0; e < NEXP; e++) cnt[e] = 0;
    #pragma unroll
    for (int c = 0; c < 8; c++) {
        int4 v = ep[c];
        #pragma unroll
        for (int e = 0; e < NEXP; e++)
            cnt[e] += (v.x == e) + (v.y == e) + (v.z == e) + (v.w == e);
    }
    #pragma unroll
    for (int e = 0; e < NEXP; e++) s[tid][e] = cnt[e];
    __syncthreads();
    for (int off = 1; off < 1024; off <<= 1) {
        int v[NEXP];
        #pragma unroll
        for (int e = 0; e < NEXP; e++)
            v[e] = s[tid][e] + ((tid >= off) ? s[tid - off][e] : 0);
        __syncthreads();
        #pragma unroll
        for (int e = 0; e < NEXP; e++) s[tid][e] = v[e];
        __syncthreads();
    }
    int basec[NEXP];
    #pragma unroll
    for (int e = 0; e < NEXP; e++) basec[e] = s[tid][e] - cnt[e];
    if (tid < NEXP) g_count[tid] = min(s[1023][tid], CAP);

    #pragma unroll
    for (int c = 0; c < 8; c++) {
        int4 v = ep[c];
        int es[4] = {v.x, v.y, v.z, v.w};
        #pragma unroll
        for (int q = 0; q < 4; q++) {
            int p = base_p + c * 4 + q;
            int eq = es[q];
            int pos = 0;
            #pragma unroll
            for (int e = 0; e < NEXP; e++)
                if (eq == e) { pos = basec[e]; basec[e] = pos + 1; }
            if (pos < CAP) {
                int slot = eq * CAP + pos;
                g_pair_slot[p] = slot;
                g_slot_token[slot] = p >> 1;
            } else {
                g_pair_slot[p] = -1;
            }
        }
    }
}

// ---------------- zbuf: RMSNorm(2x)*norm_w -> bf16 per slot ----------------
__global__ void k_zbuf(const float* __restrict__ x, const float* __restrict__ nw) {
    const int slot = blockIdx.x;
    const int e = slot / CAP;
    const int tid = threadIdx.x;
    __nv_bfloat16* zr = g_zbuf + (size_t)slot * DIM;
    const int local = slot - e * CAP;
    const int cnt = g_count[e];
    if (local >= cnt) {
        // only pad rows inside the last launched 128-row tile need zeros
        if (local < ((cnt + 127) & ~127)) {
            #pragma unroll
            for (int j = 0; j < 3; j++) zr[tid + j * 256] = __float2bfloat16(0.f);
        }
        return;
    }
    const int t = g_slot_token[slot];
    const float* xr = x + (size_t)t * DIM;
    float v[3]; float ss = 0.f;
    #pragma unroll
    for (int j = 0; j < 3; j++) { v[j] = xr[tid + j * 256]; ss += v[j] * v[j]; }
    #pragma unroll
    for (int off = 16; off; off >>= 1) ss += __shfl_xor_sync(0xffffffffu, ss, off);
    __shared__ float red[8];
    if ((tid & 31) == 0) red[tid >> 5] = ss;
    __syncthreads();
    float tot = 0.f;
    #pragma unroll
    for (int w = 0; w < 8; w++) tot += red[w];
    float scale = rsqrtf(4.f * tot / (float)DIM + 1e-6f) * 2.f;
    #pragma unroll
    for (int j = 0; j < 3; j++)
        zr[tid + j * 256] = __float2bfloat16(v[j] * scale * nw[e * DIM + tid + j * 256]);
}

// ---------------- GEMM1: gu = z @ w13^T, fused SwiGLU -> hbuf ----------------
// 128 rows x 64 h-cols (128 accum cols: 64 g + 64 u), BK=32, 2-stage cp.async
__global__ __launch_bounds__(256) void k_gemm1() {
    const int e = blockIdx.z;
    const int row0 = blockIdx.y * 128;
    if (row0 >= g_count[e]) return;
    const int jb = blockIdx.x * 64;
    __shared__ __align__(16) __nv_bfloat16 As[2][128][40];
    __shared__ __align__(16) __nv_bfloat16 Bs[2][128][40];
    const int tid = threadIdx.x, lane = tid & 31, wid = tid >> 5;
    const int wm = wid >> 1, wc = wid & 1;
    const __nv_bfloat16* Ag  = g_zbuf  + (size_t)(e * CAP + row0) * DIM;
    const __nv_bfloat16* Bgg = g_w13bf + (size_t)e * (2 * HID) * DIM + (size_t)jb * DIM;
    const __nv_bfloat16* Bgu = g_w13bf + (size_t)e * (2 * HID) * DIM + (size_t)(HID + jb) * DIM;

    float acc[2][8][4];
    #pragma unroll
    for (int i = 0; i < 2; i++)
        #pragma unroll
        for (int j = 0; j < 8; j++)
            #pragma unroll
            for (int q = 0; q < 4; q++) acc[i][j][q] = 0.f;

    // loader: 512 16B-chunks each for As/Bs per stage, 2 per thread
    auto load_tile = [&](int st, int k0) {
        #pragma unroll
        for (int h = 0; h < 2; h++) {
            int c = tid + h * 256;
            int row = c >> 2, col = (c & 3) * 8;
            cp16(&As[st][row][col], Ag + (size_t)row * DIM + k0 + col);
            const __nv_bfloat16* bsrc = (row < 64)
                ? (Bgg + (size_t)row * DIM) : (Bgu + (size_t)(row - 64) * DIM);
            cp16(&Bs[st][row][col], bsrc + k0 + col);
        }
        CP_COMMIT();
    };

    load_tile(0, 0);
    const int KT = DIM / 32;  // 24
    for (int kt = 0; kt < KT; kt++) {
        CP_WAIT0();
        __syncthreads();
        if (kt + 1 < KT) load_tile((kt + 1) & 1, (kt + 1) * 32);
        const int st = kt & 1;
        #pragma unroll
        for (int ka = 0; ka < 2; ka++) {
            uint32_t af[2][4];
            #pragma unroll
            for (int i = 0; i < 2; i++) {
                uint32_t addr = smem_u32(&As[st][wm * 32 + i * 16 + (lane & 15)][ka * 16 + ((lane >> 4) << 3)]);
                ldsm_x4(af[i][0], af[i][1], af[i][2], af[i][3], addr);
            }
            uint32_t bfm[8][2];
            #pragma unroll
            for (int jp = 0; jp < 4; jp++) {
                int j0 = jp * 2;
                int m = lane >> 3;
                int jj = j0 + (m >> 1);
                int brow = (jj < 4) ? (wc * 32 + jj * 8) : (64 + wc * 32 + (jj - 4) * 8);
                uint32_t addr = smem_u32(&Bs[st][brow + (lane & 7)][ka * 16 + ((m & 1) << 3)]);
                uint32_t r0, r1, r2, r3;
                ldsm_x4(r0, r1, r2, r3, addr);
                bfm[j0][0] = r0; bfm[j0][1] = r1;
                bfm[j0 + 1][0] = r2; bfm[j0 + 1][1] = r3;
            }
            #pragma unroll
            for (int i = 0; i < 2; i++)
                #pragma unroll
                for (int j = 0; j < 8; j++)
                    mma16816(acc[i][j], af[i], bfm[j]);
        }
    }

    // epilogue: h = silu(g) * u
    const int gid = lane >> 2, qid = lane & 3;
    __nv_bfloat16* Hb = g_hbuf + (size_t)(e * CAP + row0) * HID;
    #pragma unroll
    for (int i = 0; i < 2; i++) {
        #pragma unroll
        for (int j = 0; j < 4; j++) {
            int hc = jb + wc * 32 + j * 8 + qid * 2;
            #pragma unroll
            for (int half = 0; half < 2; half++) {
                int r = wm * 32 + i * 16 + gid + half * 8;
                float g0 = acc[i][j][half * 2 + 0], g1 = acc[i][j][half * 2 + 1];
                float u0 = acc[i][j + 4][half * 2 + 0], u1 = acc[i][j + 4][half * 2 + 1];
                float h0 = g0 * u0 / (1.f + __expf(-g0));
                float h1 = g1 * u1 / (1.f + __expf(-g1));
                *reinterpret_cast<__nv_bfloat162*>(Hb + (size_t)r * HID + hc) =
                    __floats2bfloat162_rn(h0, h1);
            }
        }
    }
}

// ---------------- GEMM2: y = h @ w2^T -> ybuf (fp32) ----------------
// 128 rows x 64 d-cols, BK=32, 2-stage cp.async
__global__ __launch_bounds__(256) void k_gemm2() {
    const int e = blockIdx.z;
    const int row0 = blockIdx.y * 128;
    if (row0 >= g_count[e]) return;
    const int db = blockIdx.x * 64;
    __shared__ __align__(16) __nv_bfloat16 As[2][128][40];
    __shared__ __align__(16) __nv_bfloat16 Bs[2][64][40];
    const int tid = threadIdx.x, lane = tid & 31, wid = tid >> 5;
    const int wm = wid >> 1, wc = wid & 1;
    const __nv_bfloat16* Ag = g_hbuf + (size_t)(e * CAP + row0) * HID;
    const __nv_bfloat16* Bg = g_w2bf + (size_t)e * DIM * HID + (size_t)db * HID;

    float acc[2][4][4];
    #pragma unroll
    for (int i = 0; i < 2; i++)
        #pragma unroll
        for (int j = 0; j < 4; j++)
            #pragma unroll
            for (int q = 0; q < 4; q++) acc[i][j][q] = 0.f;

    auto load_tile = [&](int st, int k0) {
        #pragma unroll
        for (int h = 0; h < 2; h++) {
            int c = tid + h * 256;
            int row = c >> 2, col = (c & 3) * 8;
            cp16(&As[st][row][col], Ag + (size_t)row * HID + k0 + col);
        }
        {
            int row = tid >> 2, col = (tid & 3) * 8;
            cp16(&Bs[st][row][col], Bg + (size_t)row * HID + k0 + col);
        }
        CP_COMMIT();
    };

    load_tile(0, 0);
    const int KT = HID / 32;  // 64
    for (int kt = 0; kt < KT; kt++) {
        CP_WAIT0();
        __syncthreads();
        if (kt + 1 < KT) load_tile((kt + 1) & 1, (kt + 1) * 32);
        const int st = kt & 1;
        #pragma unroll
        for (int ka = 0; ka < 2; ka++) {
            uint32_t af[2][4];
            #pragma unroll
            for (int i = 0; i < 2; i++) {
                uint32_t addr = smem_u32(&As[st][wm * 32 + i * 16 + (lane & 15)][ka * 16 + ((lane >> 4) << 3)]);
                ldsm_x4(af[i][0], af[i][1], af[i][2], af[i][3], addr);
            }
            uint32_t bfm[4][2];
            #pragma unroll
            for (int jp = 0; jp < 2; jp++) {
                int j0 = jp * 2;
                int m = lane >> 3;
                int jj = j0 + (m >> 1);
                int brow = wc * 32 + jj * 8;
                uint32_t addr = smem_u32(&Bs[st][brow + (lane & 7)][ka * 16 + ((m & 1) << 3)]);
                uint32_t r0, r1, r2, r3;
                ldsm_x4(r0, r1, r2, r3, addr);
                bfm[j0][0] = r0; bfm[j0][1] = r1;
                bfm[j0 + 1][0] = r2; bfm[j0 + 1][1] = r3;
            }
            #pragma unroll
            for (int i = 0; i < 2; i++)
                #pragma unroll
                for (int j = 0; j < 4; j++)
                    mma16816(acc[i][j], af[i], bfm[j]);
        }
    }

    const int gid = lane >> 2, qid = lane & 3;
    float* Yb = g_ybuf + (size_t)(e * CAP + row0) * DIM;
    #pragma unroll
    for (int i = 0; i < 2; i++) {
        #pragma unroll
        for (int j = 0; j < 4; j++) {
            int dc = db + wc * 32 + j * 8 + qid * 2;
            #pragma unroll
            for (int half = 0; half < 2; half++) {
                int r = wm * 32 + i * 16 + gid + half * 8;
                float2 v = make_float2(acc[i][j][half * 2 + 0], acc[i][j][half * 2 + 1]);
                *reinterpret_cast<float2*>(Yb + (size_t)r * DIM + dc) = v;
            }
        }
    }
}

// ---------------- combine ----------------
__global__ void k_combine(const float* __restrict__ x, float* __restrict__ out) {
    const int t = blockIdx.x, tid = threadIdx.x;
    int s0 = g_pair_slot[2 * t], s1 = g_pair_slot[2 * t + 1];
    float w0 = g_pair_weight[2 * t], w1 = g_pair_weight[2 * t + 1];
    if (s0 < 0) w0 = 0.f;
    if (s1 < 0) w1 = 0.f;
    const float wsum = w0 + w1;
    const float* y0 = g_ybuf + (size_t)(s0 < 0 ? 0 : s0) * DIM;
    const float* y1 = g_ybuf + (size_t)(s1 < 0 ? 0 : s1) * DIM;
    #pragma unroll
    for (int j = 0; j < 3; j++) {
        int d = tid + j * 256;
        float v = wsum * x[(size_t)t * DIM + d];
        if (s0 >= 0) v += w0 * y0[d];
        if (s1 >= 0) v += w1 * y1[d];
        out[(size_t)t * DIM + d] = v;
    }
}

// ---------------- launch ----------------
extern "C" void kernel_launch(void* const* d_in, const int* in_sizes, int n_in,
                              void* d_out, int out_size) {
    const float* x      = (const float*)d_in[0];
    const float* gate_w = (const float*)d_in[1];
    const float* w13    = (const float*)d_in[2];
    const float* w2     = (const float*)d_in[3];
    const float* norm_w = (const float*)d_in[4];
    float* out = (float*)d_out;

    k_conv13<<<(NEXP * 2 * HID * DIM) / 1024, 256>>>(w13);
    k_conv2 <<<(NEXP * DIM * HID) / 1024, 256>>>(w2);
    k_router<<<N_TOK / 8, 256>>>(x, gate_w);
    k_dispatch<<<1, 1024>>>();
    k_zbuf<<<ECAP, 256>>>(x, norm_w);
    k_gemm1<<<dim3(HID / 64, CAP / 128, NEXP), 256>>>();
    k_gemm2<<<dim3(DIM / 64, CAP / 128, NEXP), 256>>>();
    k_combine<<<N_TOK, 256>>>(x, out);
}